// round 1
// baseline (speedup 1.0000x reference)
#include <cuda_runtime.h>
#include <cuda_bf16.h>

// ---------------------------------------------------------------------------
// EGraphSAGE, 2 layers, restructured:
//   Layer l edge GEMM  relu(concat(hn[u],hn[v])@We+b) == relu(P[u]+Q[v]+b)
//   with P = hn@We[0:128], Q = hn@We[128:256]  (node-level GEMMs, 32x cheaper)
//   he1 is never materialized: fused into the layer-2 scatter.
// Pipeline:
//   zero(msum1,msum2,deg)
//   scatter1: msum1[v] += concat(nfeats[u], efeats[e]); deg[v] += 1
//   hn1  = relu([nfeats | msum1/deg] @ W1a + b1a)
//   PQ1  = hn1 @ [W1e_top | W1e_bot]
//   edge1+scatter2: he1 = relu(P1[u]+Q1[v]+b1e);
//                   msum2[v] += concat(hn1[u], he1)
//   hn2  = relu([hn1 | msum2/deg] @ W2a + b2a)        -> d_out[0 : 50000*128]
//   PQ2  = hn2 @ [W2e_top | W2e_bot]
//   edge2: he2 = relu(P2[u]+Q2[v]+b2e)                -> d_out[50000*128 : ]
// ---------------------------------------------------------------------------

#define N_NODES 50000
#define N_EDGES 800000

// Scratch (device globals: no allocation allowed in kernel_launch)
__device__ float g_msum1[N_NODES * 128];
__device__ float g_deg  [N_NODES];
__device__ float g_hn1  [N_NODES * 128];
__device__ float g_PQ1  [N_NODES * 256];
__device__ float g_msum2[N_NODES * 256];
__device__ float g_PQ2  [N_NODES * 256];

// ---------------------------------------------------------------------------
__global__ void zero_kernel(float4* __restrict__ p, int n4) {
    int i = blockIdx.x * blockDim.x + threadIdx.x;
    int stride = gridDim.x * blockDim.x;
    float4 z = make_float4(0.f, 0.f, 0.f, 0.f);
    for (; i < n4; i += stride) p[i] = z;
}

// ---------------------------------------------------------------------------
// scatter1: one warp per edge, lane handles 4 features (f = 4*lane).
// msg = concat(nfeats[u] (64), efeats[e] (64)) -> atomicAdd into msum1[v].
__global__ void scatter1_kernel(const float* __restrict__ nfeats,
                                const float* __restrict__ efeats,
                                const int* __restrict__ u,
                                const int* __restrict__ v,
                                float* __restrict__ msum1,
                                float* __restrict__ deg,
                                int n_edges) {
    int e = (blockIdx.x * blockDim.x + threadIdx.x) >> 5;
    int lane = threadIdx.x & 31;
    if (e >= n_edges) return;
    int uu = u[e], vv = v[e];
    float4 val;
    if (lane < 16)
        val = *(const float4*)(nfeats + uu * 64 + lane * 4);
    else
        val = *(const float4*)(efeats + e * 64 + (lane - 16) * 4);
    float* dst = msum1 + vv * 128 + lane * 4;
    atomicAdd(dst + 0, val.x);
    atomicAdd(dst + 1, val.y);
    atomicAdd(dst + 2, val.z);
    atomicAdd(dst + 3, val.w);
    if (lane == 0) atomicAdd(deg + vv, 1.0f);
}

// ---------------------------------------------------------------------------
// Generic node GEMM: out[row, off + 0:128] = act( [A1 | A2/deg] @ W + bias )
//   A1: [n_rows, K1], A2: [n_rows, K2] (scaled by 1/max(deg,1) if deg != null)
//   W : [(K1+K2), 128] row-major
// Tile: 32 rows x 128 cols per block, 256 threads, 4x4 register tile.
#define GROWS 32
#define KC 32
__global__ __launch_bounds__(256)
void gemm_node_kernel(const float* __restrict__ A1, int K1,
                      const float* __restrict__ A2, int K2,
                      const float* __restrict__ deg,
                      const float* __restrict__ W,
                      const float* __restrict__ bias,
                      int do_relu,
                      float* __restrict__ out, int out_stride, int out_off,
                      int n_rows) {
    __shared__ float s_in[GROWS][KC];
    __shared__ float s_w[KC][128];
    __shared__ float s_scale[GROWS];

    int tid = threadIdx.x;
    int tx = tid & 31;        // col group: cols tx*4 .. tx*4+3
    int ty = tid >> 5;        // row group: rows ty*4 .. ty*4+3
    int row0 = blockIdx.x * GROWS;
    int K = K1 + K2;

    if (tid < GROWS) {
        int r = row0 + tid;
        float d = 1.0f;
        if (deg != nullptr && r < n_rows) d = deg[r];
        s_scale[tid] = 1.0f / fmaxf(d, 1.0f);
    }
    __syncthreads();

    float acc[4][4];
#pragma unroll
    for (int n = 0; n < 4; n++)
#pragma unroll
        for (int c = 0; c < 4; c++) acc[n][c] = 0.f;

    for (int kc0 = 0; kc0 < K; kc0 += KC) {
        // load input tile: 32 rows x 32 k (4 elems/thread)
#pragma unroll
        for (int p = 0; p < 4; p++) {
            int i = tid + p * 256;
            int r = i >> 5, kk = i & 31;
            int row = row0 + r;
            int k = kc0 + kk;
            float val = 0.f;
            if (row < n_rows) {
                if (k < K1) val = A1[row * K1 + k];
                else        val = A2[row * K2 + (k - K1)] * s_scale[r];
            }
            s_in[r][kk] = val;
        }
        // load weight tile: 32 k x 128 cols (16 elems/thread)
#pragma unroll
        for (int p = 0; p < 16; p++) {
            int i = tid + p * 256;
            int kk = i >> 7, col = i & 127;
            s_w[kk][col] = W[(kc0 + kk) * 128 + col];
        }
        __syncthreads();

#pragma unroll
        for (int kk = 0; kk < KC; kk++) {
            float4 w = *(const float4*)&s_w[kk][tx * 4];
            float a0 = s_in[ty * 4 + 0][kk];
            float a1 = s_in[ty * 4 + 1][kk];
            float a2 = s_in[ty * 4 + 2][kk];
            float a3 = s_in[ty * 4 + 3][kk];
            acc[0][0] += a0 * w.x; acc[0][1] += a0 * w.y; acc[0][2] += a0 * w.z; acc[0][3] += a0 * w.w;
            acc[1][0] += a1 * w.x; acc[1][1] += a1 * w.y; acc[1][2] += a1 * w.z; acc[1][3] += a1 * w.w;
            acc[2][0] += a2 * w.x; acc[2][1] += a2 * w.y; acc[2][2] += a2 * w.z; acc[2][3] += a2 * w.w;
            acc[3][0] += a3 * w.x; acc[3][1] += a3 * w.y; acc[3][2] += a3 * w.z; acc[3][3] += a3 * w.w;
        }
        __syncthreads();
    }

    int col = tx * 4;
    float4 b = make_float4(0.f, 0.f, 0.f, 0.f);
    if (bias != nullptr) b = *(const float4*)(bias + col);
#pragma unroll
    for (int n = 0; n < 4; n++) {
        int row = row0 + ty * 4 + n;
        if (row >= n_rows) break;
        float4 o;
        o.x = acc[n][0] + b.x;
        o.y = acc[n][1] + b.y;
        o.z = acc[n][2] + b.z;
        o.w = acc[n][3] + b.w;
        if (do_relu) {
            o.x = fmaxf(o.x, 0.f); o.y = fmaxf(o.y, 0.f);
            o.z = fmaxf(o.z, 0.f); o.w = fmaxf(o.w, 0.f);
        }
        *(float4*)(out + row * out_stride + out_off + col) = o;
    }
}

// ---------------------------------------------------------------------------
// edge1 + scatter2 fused: one warp per edge.
//   he1 = relu(P1[u] + Q1[v] + b1e)         (never written to memory)
//   msum2[v][0:128]   += hn1[u]
//   msum2[v][128:256] += he1
__global__ void edge1_scatter2_kernel(const float* __restrict__ PQ1,
                                      const float* __restrict__ hn1,
                                      const float* __restrict__ b1e,
                                      const int* __restrict__ u,
                                      const int* __restrict__ v,
                                      float* __restrict__ msum2,
                                      int n_edges) {
    int e = (blockIdx.x * blockDim.x + threadIdx.x) >> 5;
    int lane = threadIdx.x & 31;
    if (e >= n_edges) return;
    int uu = u[e], vv = v[e];
    int j = lane * 4;
    float4 p = *(const float4*)(PQ1 + uu * 256 + j);
    float4 q = *(const float4*)(PQ1 + vv * 256 + 128 + j);
    float4 b = *(const float4*)(b1e + j);
    float4 h;
    h.x = fmaxf(p.x + q.x + b.x, 0.f);
    h.y = fmaxf(p.y + q.y + b.y, 0.f);
    h.z = fmaxf(p.z + q.z + b.z, 0.f);
    h.w = fmaxf(p.w + q.w + b.w, 0.f);
    float* d2 = msum2 + vv * 256;
    atomicAdd(d2 + 128 + j + 0, h.x);
    atomicAdd(d2 + 128 + j + 1, h.y);
    atomicAdd(d2 + 128 + j + 2, h.z);
    atomicAdd(d2 + 128 + j + 3, h.w);
    float4 hu = *(const float4*)(hn1 + uu * 128 + j);
    atomicAdd(d2 + j + 0, hu.x);
    atomicAdd(d2 + j + 1, hu.y);
    atomicAdd(d2 + j + 2, hu.z);
    atomicAdd(d2 + j + 3, hu.w);
}

// ---------------------------------------------------------------------------
// edge2: he2 = relu(P2[u] + Q2[v] + b2e) -> out_he (coalesced float4 stores)
__global__ void edge2_kernel(const float* __restrict__ PQ2,
                             const float* __restrict__ b2e,
                             const int* __restrict__ u,
                             const int* __restrict__ v,
                             float* __restrict__ out_he,
                             int n_edges) {
    int e = (blockIdx.x * blockDim.x + threadIdx.x) >> 5;
    int lane = threadIdx.x & 31;
    if (e >= n_edges) return;
    int uu = u[e], vv = v[e];
    int j = lane * 4;
    float4 p = *(const float4*)(PQ2 + uu * 256 + j);
    float4 q = *(const float4*)(PQ2 + vv * 256 + 128 + j);
    float4 b = *(const float4*)(b2e + j);
    float4 o;
    o.x = fmaxf(p.x + q.x + b.x, 0.f);
    o.y = fmaxf(p.y + q.y + b.y, 0.f);
    o.z = fmaxf(p.z + q.z + b.z, 0.f);
    o.w = fmaxf(p.w + q.w + b.w, 0.f);
    *(float4*)(out_he + e * 128 + j) = o;
}

// ---------------------------------------------------------------------------
extern "C" void kernel_launch(void* const* d_in, const int* in_sizes, int n_in,
                              void* d_out, int out_size) {
    const float* nfeats = (const float*)d_in[0];
    const float* efeats = (const float*)d_in[1];
    const float* W1a_w  = (const float*)d_in[2];
    const float* W1a_b  = (const float*)d_in[3];
    const float* W1e_w  = (const float*)d_in[4];
    const float* W1e_b  = (const float*)d_in[5];
    const float* W2a_w  = (const float*)d_in[6];
    const float* W2a_b  = (const float*)d_in[7];
    const float* W2e_w  = (const float*)d_in[8];
    const float* W2e_b  = (const float*)d_in[9];
    const int*   u      = (const int*)d_in[10];
    const int*   v      = (const int*)d_in[11];
    float* out = (float*)d_out;

    float *msum1, *deg, *hn1, *PQ1, *msum2, *PQ2;
    cudaGetSymbolAddress((void**)&msum1, g_msum1);
    cudaGetSymbolAddress((void**)&deg,   g_deg);
    cudaGetSymbolAddress((void**)&hn1,   g_hn1);
    cudaGetSymbolAddress((void**)&PQ1,   g_PQ1);
    cudaGetSymbolAddress((void**)&msum2, g_msum2);
    cudaGetSymbolAddress((void**)&PQ2,   g_PQ2);

    const int N = N_NODES, E = N_EDGES;
    const int gemm_grid = (N + GROWS - 1) / GROWS;
    const int edge_grid = (E * 32 + 255) / 256;

    zero_kernel<<<2048, 256>>>((float4*)msum1, N * 128 / 4);
    zero_kernel<<<2048, 256>>>((float4*)msum2, N * 256 / 4);
    zero_kernel<<<64,   256>>>((float4*)deg,   N / 4);

    // Layer 1 aggregation
    scatter1_kernel<<<edge_grid, 256>>>(nfeats, efeats, u, v, msum1, deg, E);

    // hn1 = relu([nfeats | msum1/deg] @ W1a + b1a)
    gemm_node_kernel<<<gemm_grid, 256>>>(nfeats, 64, msum1, 128, deg,
                                         W1a_w, W1a_b, 1, hn1, 128, 0, N);
    // PQ1 = hn1 @ [W1e_top | W1e_bot]
    gemm_node_kernel<<<gemm_grid, 256>>>(hn1, 128, nullptr, 0, nullptr,
                                         W1e_w,             nullptr, 0, PQ1, 256, 0,   N);
    gemm_node_kernel<<<gemm_grid, 256>>>(hn1, 128, nullptr, 0, nullptr,
                                         W1e_w + 128 * 128, nullptr, 0, PQ1, 256, 128, N);

    // he1 (in registers) + layer-2 aggregation
    edge1_scatter2_kernel<<<edge_grid, 256>>>(PQ1, hn1, W1e_b, u, v, msum2, E);

    // hn2 = relu([hn1 | msum2/deg] @ W2a + b2a)  -> d_out node block
    gemm_node_kernel<<<gemm_grid, 256>>>(hn1, 128, msum2, 256, deg,
                                         W2a_w, W2a_b, 1, out, 128, 0, N);
    // PQ2 = hn2 @ [W2e_top | W2e_bot]
    gemm_node_kernel<<<gemm_grid, 256>>>(out, 128, nullptr, 0, nullptr,
                                         W2e_w,             nullptr, 0, PQ2, 256, 0,   N);
    gemm_node_kernel<<<gemm_grid, 256>>>(out, 128, nullptr, 0, nullptr,
                                         W2e_w + 128 * 128, nullptr, 0, PQ2, 256, 128, N);

    // he2 -> d_out edge block
    edge2_kernel<<<edge_grid, 256>>>(PQ2, W2e_b, u, v, out + N * 128, E);
}

// round 2
// speedup vs baseline: 1.1318x; 1.1318x over previous
#include <cuda_runtime.h>
#include <cuda_bf16.h>

// ---------------------------------------------------------------------------
// EGraphSAGE, 2 layers, restructured (see R1). R2 changes:
//   * red.global.add.v4.f32 for all scatter atomics (4x fewer L2 atomic ops)
//   * 64-row GEMM tiles with 8x4 register accumulators (2x FFMA density)
//   * P|Q edge-weight GEMMs fused into one launch via blockIdx.y
// ---------------------------------------------------------------------------

#define N_NODES 50000
#define N_EDGES 800000

__device__ float g_msum1[N_NODES * 128];
__device__ float g_deg  [N_NODES];
__device__ float g_hn1  [N_NODES * 128];
__device__ float g_PQ1  [N_NODES * 256];
__device__ float g_msum2[N_NODES * 256];
__device__ float g_PQ2  [N_NODES * 256];

// Vectorized non-returning global reduction (sm_90+)
__device__ __forceinline__ void red_add_v4(float* addr, float4 v) {
    asm volatile("red.global.add.v4.f32 [%0], {%1, %2, %3, %4};"
                 :: "l"(addr), "f"(v.x), "f"(v.y), "f"(v.z), "f"(v.w)
                 : "memory");
}

// ---------------------------------------------------------------------------
__global__ void zero_kernel(float4* __restrict__ p, int n4) {
    int i = blockIdx.x * blockDim.x + threadIdx.x;
    int stride = gridDim.x * blockDim.x;
    float4 z = make_float4(0.f, 0.f, 0.f, 0.f);
    for (; i < n4; i += stride) p[i] = z;
}

// ---------------------------------------------------------------------------
// scatter1: one warp per edge, lane handles 4 features.
// msg = concat(nfeats[u] (64), efeats[e] (64)) -> red.v4 into msum1[v].
__global__ void scatter1_kernel(const float* __restrict__ nfeats,
                                const float* __restrict__ efeats,
                                const int* __restrict__ u,
                                const int* __restrict__ v,
                                float* __restrict__ msum1,
                                float* __restrict__ deg,
                                int n_edges) {
    int e = (blockIdx.x * blockDim.x + threadIdx.x) >> 5;
    int lane = threadIdx.x & 31;
    if (e >= n_edges) return;
    int uu = u[e], vv = v[e];
    float4 val;
    if (lane < 16)
        val = *(const float4*)(nfeats + uu * 64 + lane * 4);
    else
        val = *(const float4*)(efeats + e * 64 + (lane - 16) * 4);
    red_add_v4(msum1 + vv * 128 + lane * 4, val);
    if (lane == 0) atomicAdd(deg + vv, 1.0f);
}

// ---------------------------------------------------------------------------
// Node GEMM: out[row, out_off + by*128 + 0:128] =
//     act( [A1 | A2/deg] @ W[by] + bias ),  W[by] = W + by*K*128
// Tile: 64 rows x 128 cols, 256 threads, 8x4 register tile, KC=32.
#define GROWS 64
#define KC 32
__global__ __launch_bounds__(256)
void gemm_node_kernel(const float* __restrict__ A1, int K1,
                      const float* __restrict__ A2, int K2,
                      const float* __restrict__ deg,
                      const float* __restrict__ W,
                      const float* __restrict__ bias,
                      int do_relu,
                      float* __restrict__ out, int out_stride, int out_off,
                      int n_rows) {
    __shared__ float s_in[GROWS][KC];
    __shared__ float s_w[KC][128];
    __shared__ float s_scale[GROWS];

    int tid = threadIdx.x;
    int tx = tid & 31;        // col group: cols tx*4 .. tx*4+3
    int ty = tid >> 5;        // row group: rows ty*8 .. ty*8+7
    int row0 = blockIdx.x * GROWS;
    int K = K1 + K2;
    const float* Wb = W + (size_t)blockIdx.y * K * 128;
    int off = out_off + blockIdx.y * 128;

    if (tid < GROWS) {
        int r = row0 + tid;
        float d = 1.0f;
        if (deg != nullptr && r < n_rows) d = deg[r];
        s_scale[tid] = 1.0f / fmaxf(d, 1.0f);
    }
    __syncthreads();

    float acc[8][4];
#pragma unroll
    for (int n = 0; n < 8; n++)
#pragma unroll
        for (int c = 0; c < 4; c++) acc[n][c] = 0.f;

    for (int kc0 = 0; kc0 < K; kc0 += KC) {
        // input tile: 64 rows x 32 k (8 elems/thread)
#pragma unroll
        for (int p = 0; p < 8; p++) {
            int i = tid + p * 256;
            int r = i >> 5, kk = i & 31;
            int row = row0 + r;
            int k = kc0 + kk;
            float val = 0.f;
            if (row < n_rows) {
                if (k < K1) val = A1[row * K1 + k];
                else        val = A2[row * K2 + (k - K1)] * s_scale[r];
            }
            s_in[r][kk] = val;
        }
        // weight tile: 32 k x 128 cols (16 elems/thread)
#pragma unroll
        for (int p = 0; p < 16; p++) {
            int i = tid + p * 256;
            int kk = i >> 7, col = i & 127;
            s_w[kk][col] = Wb[(kc0 + kk) * 128 + col];
        }
        __syncthreads();

#pragma unroll
        for (int kk = 0; kk < KC; kk++) {
            float4 w = *(const float4*)&s_w[kk][tx * 4];
#pragma unroll
            for (int n = 0; n < 8; n++) {
                float a = s_in[ty * 8 + n][kk];
                acc[n][0] += a * w.x;
                acc[n][1] += a * w.y;
                acc[n][2] += a * w.z;
                acc[n][3] += a * w.w;
            }
        }
        __syncthreads();
    }

    int col = tx * 4;
    float4 b = make_float4(0.f, 0.f, 0.f, 0.f);
    if (bias != nullptr) b = *(const float4*)(bias + col);
#pragma unroll
    for (int n = 0; n < 8; n++) {
        int row = row0 + ty * 8 + n;
        if (row >= n_rows) break;
        float4 o;
        o.x = acc[n][0] + b.x;
        o.y = acc[n][1] + b.y;
        o.z = acc[n][2] + b.z;
        o.w = acc[n][3] + b.w;
        if (do_relu) {
            o.x = fmaxf(o.x, 0.f); o.y = fmaxf(o.y, 0.f);
            o.z = fmaxf(o.z, 0.f); o.w = fmaxf(o.w, 0.f);
        }
        *(float4*)(out + (size_t)row * out_stride + off + col) = o;
    }
}

// ---------------------------------------------------------------------------
// edge1 + scatter2 fused: one warp per edge.
//   he1 = relu(P1[u] + Q1[v] + b1e)  (registers only)
//   msum2[v][0:128]   += hn1[u]
//   msum2[v][128:256] += he1
__global__ void edge1_scatter2_kernel(const float* __restrict__ PQ1,
                                      const float* __restrict__ hn1,
                                      const float* __restrict__ b1e,
                                      const int* __restrict__ u,
                                      const int* __restrict__ v,
                                      float* __restrict__ msum2,
                                      int n_edges) {
    int e = (blockIdx.x * blockDim.x + threadIdx.x) >> 5;
    int lane = threadIdx.x & 31;
    if (e >= n_edges) return;
    int uu = u[e], vv = v[e];
    int j = lane * 4;
    float4 p = *(const float4*)(PQ1 + (size_t)uu * 256 + j);
    float4 q = *(const float4*)(PQ1 + (size_t)vv * 256 + 128 + j);
    float4 b = *(const float4*)(b1e + j);
    float4 h;
    h.x = fmaxf(p.x + q.x + b.x, 0.f);
    h.y = fmaxf(p.y + q.y + b.y, 0.f);
    h.z = fmaxf(p.z + q.z + b.z, 0.f);
    h.w = fmaxf(p.w + q.w + b.w, 0.f);
    float* d2 = msum2 + (size_t)vv * 256;
    red_add_v4(d2 + 128 + j, h);
    float4 hu = *(const float4*)(hn1 + (size_t)uu * 128 + j);
    red_add_v4(d2 + j, hu);
}

// ---------------------------------------------------------------------------
// edge2: he2 = relu(P2[u] + Q2[v] + b2e) -> out_he (coalesced float4 stores)
__global__ void edge2_kernel(const float* __restrict__ PQ2,
                             const float* __restrict__ b2e,
                             const int* __restrict__ u,
                             const int* __restrict__ v,
                             float* __restrict__ out_he,
                             int n_edges) {
    int e = (blockIdx.x * blockDim.x + threadIdx.x) >> 5;
    int lane = threadIdx.x & 31;
    if (e >= n_edges) return;
    int uu = u[e], vv = v[e];
    int j = lane * 4;
    float4 p = *(const float4*)(PQ2 + (size_t)uu * 256 + j);
    float4 q = *(const float4*)(PQ2 + (size_t)vv * 256 + 128 + j);
    float4 b = *(const float4*)(b2e + j);
    float4 o;
    o.x = fmaxf(p.x + q.x + b.x, 0.f);
    o.y = fmaxf(p.y + q.y + b.y, 0.f);
    o.z = fmaxf(p.z + q.z + b.z, 0.f);
    o.w = fmaxf(p.w + q.w + b.w, 0.f);
    *(float4*)(out_he + (size_t)e * 128 + j) = o;
}

// ---------------------------------------------------------------------------
extern "C" void kernel_launch(void* const* d_in, const int* in_sizes, int n_in,
                              void* d_out, int out_size) {
    const float* nfeats = (const float*)d_in[0];
    const float* efeats = (const float*)d_in[1];
    const float* W1a_w  = (const float*)d_in[2];
    const float* W1a_b  = (const float*)d_in[3];
    const float* W1e_w  = (const float*)d_in[4];
    const float* W1e_b  = (const float*)d_in[5];
    const float* W2a_w  = (const float*)d_in[6];
    const float* W2a_b  = (const float*)d_in[7];
    const float* W2e_w  = (const float*)d_in[8];
    const float* W2e_b  = (const float*)d_in[9];
    const int*   u      = (const int*)d_in[10];
    const int*   v      = (const int*)d_in[11];
    float* out = (float*)d_out;

    float *msum1, *deg, *hn1, *PQ1, *msum2, *PQ2;
    cudaGetSymbolAddress((void**)&msum1, g_msum1);
    cudaGetSymbolAddress((void**)&deg,   g_deg);
    cudaGetSymbolAddress((void**)&hn1,   g_hn1);
    cudaGetSymbolAddress((void**)&PQ1,   g_PQ1);
    cudaGetSymbolAddress((void**)&msum2, g_msum2);
    cudaGetSymbolAddress((void**)&PQ2,   g_PQ2);

    const int N = N_NODES, E = N_EDGES;
    const int gemm_gx = (N + GROWS - 1) / GROWS;
    const int edge_grid = (E * 32 + 255) / 256;

    zero_kernel<<<2048, 256>>>((float4*)msum1, N * 128 / 4);
    zero_kernel<<<2048, 256>>>((float4*)msum2, N * 256 / 4);
    zero_kernel<<<64,   256>>>((float4*)deg,   N / 4);

    // Layer 1 aggregation
    scatter1_kernel<<<edge_grid, 256>>>(nfeats, efeats, u, v, msum1, deg, E);

    // hn1 = relu([nfeats | msum1/deg] @ W1a + b1a)
    gemm_node_kernel<<<dim3(gemm_gx, 1), 256>>>(nfeats, 64, msum1, 128, deg,
                                                W1a_w, W1a_b, 1, hn1, 128, 0, N);
    // PQ1 = hn1 @ [W1e_top | W1e_bot]  (blockIdx.y selects P/Q strip)
    gemm_node_kernel<<<dim3(gemm_gx, 2), 256>>>(hn1, 128, nullptr, 0, nullptr,
                                                W1e_w, nullptr, 0, PQ1, 256, 0, N);

    // he1 (registers) + layer-2 aggregation
    edge1_scatter2_kernel<<<edge_grid, 256>>>(PQ1, hn1, W1e_b, u, v, msum2, E);

    // hn2 = relu([hn1 | msum2/deg] @ W2a + b2a)  -> d_out node block
    gemm_node_kernel<<<dim3(gemm_gx, 1), 256>>>(hn1, 128, msum2, 256, deg,
                                                W2a_w, W2a_b, 1, out, 128, 0, N);
    // PQ2 = hn2 @ [W2e_top | W2e_bot]
    gemm_node_kernel<<<dim3(gemm_gx, 2), 256>>>(out, 128, nullptr, 0, nullptr,
                                                W2e_w, nullptr, 0, PQ2, 256, 0, N);

    // he2 -> d_out edge block
    edge2_kernel<<<edge_grid, 256>>>(PQ2, W2e_b, u, v, out + N * 128, E);
}

// round 4
// speedup vs baseline: 2.3333x; 2.0616x over previous
#include <cuda_runtime.h>
#include <cuda_bf16.h>
#include <cstdint>

// ---------------------------------------------------------------------------
// EGraphSAGE, 2 layers. R4: node GEMMs on mma.sync (HMMA, base sm_103 ISA —
// tcgen05 is rejected by this harness's ptxas target). fp32 via bf16 hi/lo
// 3-product emulation. Edge GEMMs factored as relu(P[u]+Q[v]+b); he1 fused
// into the layer-2 scatter. red.global.add.v4.f32 for all scatters.
// ---------------------------------------------------------------------------

#define N_NODES 50000
#define N_EDGES 800000

__device__ float g_msum1[N_NODES * 128];
__device__ float g_deg  [N_NODES];
__device__ float g_hn1  [N_NODES * 128];
__device__ float g_PQ1  [N_NODES * 256];
__device__ float g_msum2[N_NODES * 256];
__device__ float g_PQ2  [N_NODES * 256];
// transposed hi/lo bf16 weights, [N=128 x K] K-major, blocks packed:
// W1a(K=192) | W1eP(128) | W1eQ(128) | W2a(384) | W2eP(128) | W2eQ(128)
__device__ __nv_bfloat16 g_wt_h[128 * 1088];
__device__ __nv_bfloat16 g_wt_l[128 * 1088];

// ---------------------------------------------------------------------------
__device__ __forceinline__ void red_add_v4(float* addr, float4 v) {
    asm volatile("red.global.add.v4.f32 [%0], {%1, %2, %3, %4};"
                 :: "l"(addr), "f"(v.x), "f"(v.y), "f"(v.z), "f"(v.w)
                 : "memory");
}
__device__ __forceinline__ uint32_t smem_u32(const void* p) {
    uint32_t a;
    asm("{ .reg .u64 t; cvta.to.shared.u64 t, %1; cvt.u32.u64 %0, t; }"
        : "=r"(a) : "l"(p));
    return a;
}

#define LDSM4(r, addr) \
    asm volatile("ldmatrix.sync.aligned.m8n8.x4.shared.b16 {%0,%1,%2,%3}, [%4];" \
                 : "=r"((r)[0]), "=r"((r)[1]), "=r"((r)[2]), "=r"((r)[3]) \
                 : "r"(addr))

#define MMA16816(c, a, b0, b1) \
    asm volatile("mma.sync.aligned.m16n8k16.row.col.f32.bf16.bf16.f32 " \
                 "{%0,%1,%2,%3}, {%4,%5,%6,%7}, {%8,%9}, {%0,%1,%2,%3};" \
                 : "+f"((c)[0]), "+f"((c)[1]), "+f"((c)[2]), "+f"((c)[3]) \
                 : "r"((a)[0]), "r"((a)[1]), "r"((a)[2]), "r"((a)[3]), \
                   "r"(b0), "r"(b1))

// ---------------------------------------------------------------------------
__global__ void zero_kernel(float4* __restrict__ p, int n4) {
    int i = blockIdx.x * blockDim.x + threadIdx.x;
    int stride = gridDim.x * blockDim.x;
    float4 z = make_float4(0.f, 0.f, 0.f, 0.f);
    for (; i < n4; i += stride) p[i] = z;
}

// ---------------------------------------------------------------------------
// Weight transpose + hi/lo bf16 split: W [K x 128] fp32 -> wt[n*K + k]
__global__ void wconv_kernel(const float* __restrict__ W, int K,
                             __nv_bfloat16* __restrict__ th,
                             __nv_bfloat16* __restrict__ tl) {
    int i = blockIdx.x * blockDim.x + threadIdx.x;
    if (i >= 128 * K) return;
    int n = i / K, k = i - n * K;
    float w = W[k * 128 + n];
    __nv_bfloat16 h = __float2bfloat16(w);
    th[i] = h;
    tl[i] = __float2bfloat16(w - __bfloat162float(h));
}

// ---------------------------------------------------------------------------
// scatter1: one warp per edge; red.v4 of concat(nfeats[u], efeats[e]) into msum1[v]
__global__ void scatter1_kernel(const float* __restrict__ nfeats,
                                const float* __restrict__ efeats,
                                const int* __restrict__ u,
                                const int* __restrict__ v,
                                float* __restrict__ msum1,
                                float* __restrict__ deg,
                                int n_edges) {
    int e = (blockIdx.x * blockDim.x + threadIdx.x) >> 5;
    int lane = threadIdx.x & 31;
    if (e >= n_edges) return;
    int uu = u[e], vv = v[e];
    float4 val;
    if (lane < 16)
        val = *(const float4*)(nfeats + (size_t)uu * 64 + lane * 4);
    else
        val = *(const float4*)(efeats + (size_t)e * 64 + (lane - 16) * 4);
    red_add_v4(msum1 + (size_t)vv * 128 + lane * 4, val);
    if (lane == 0) atomicAdd(deg + vv, 1.0f);
}

// ---------------------------------------------------------------------------
// HMMA node GEMM: 128 rows x 128 cols per block, 8 warps (4 row-groups x 2
// col-groups), K chunks of 32. fp32 = bf16 hi/lo 3-product.
// out[row, out_off_base + by*128 + c] = act([A1 | A2/deg] @ W + bias)
#define APAD 40   // smem k-stride (bf16 elems): 80B rows -> conflict-free ldmatrix

__global__ __launch_bounds__(256, 2)
void gemm_mma_kernel(const float* __restrict__ A1, int K1,
                     const float* __restrict__ A2, int K2,
                     const float* __restrict__ deg,
                     const __nv_bfloat16* __restrict__ wt_h,
                     const __nv_bfloat16* __restrict__ wt_l,
                     int wt_y_stride,
                     const float* __restrict__ bias, int do_relu,
                     float* __restrict__ out, int out_stride, int out_off_base,
                     int n_rows) {
    __shared__ __nv_bfloat16 sAh[128 * APAD];
    __shared__ __nv_bfloat16 sAl[128 * APAD];
    __shared__ __nv_bfloat16 sWh[128 * APAD];
    __shared__ __nv_bfloat16 sWl[128 * APAD];
    __shared__ float s_scale[128];

    int tid = threadIdx.x;
    int wid = tid >> 5, lane = tid & 31;
    int wr = wid & 3;           // warp row group: rows wr*32 .. +31
    int wc = wid >> 2;          // warp col group: cols wc*64 .. +63
    int row0 = blockIdx.x * 128;
    int K = K1 + K2;
    const __nv_bfloat16* Wh = wt_h + (size_t)blockIdx.y * wt_y_stride;
    const __nv_bfloat16* Wl = wt_l + (size_t)blockIdx.y * wt_y_stride;
    int out_off = out_off_base + blockIdx.y * 128;

    if (tid < 128) {
        int r = row0 + tid;
        float d = 1.f;
        if (deg != nullptr && r < n_rows) d = deg[r];
        s_scale[tid] = 1.f / fmaxf(d, 1.f);
    }
    __syncthreads();

    float acc[2][8][4];
#pragma unroll
    for (int mi = 0; mi < 2; mi++)
#pragma unroll
        for (int nj = 0; nj < 8; nj++)
#pragma unroll
            for (int c = 0; c < 4; c++) acc[mi][nj][c] = 0.f;

    uint32_t sAh_b = smem_u32(sAh), sAl_b = smem_u32(sAl);
    uint32_t sWh_b = smem_u32(sWh), sWl_b = smem_u32(sWl);

    int sub = tid & 3;          // k-subgroup: 8 bf16 each
    int r0 = tid >> 2;          // 0..63 (handles rows r0 and r0+64)
    int nchunks = K >> 5;

    for (int c = 0; c < nchunks; c++) {
        int kc0 = c << 5;
        int kg = kc0 + sub * 8;
        // --- stage A (convert fp32 -> hi/lo bf16)
#pragma unroll
        for (int half = 0; half < 2; half++) {
            int r = r0 + half * 64;
            int row = row0 + r;
            float vv[8];
            if (row < n_rows) {
                const float* src;
                int kk;
                float sc = 1.f;
                if (kg < K1) { src = A1 + (size_t)row * K1; kk = kg; }
                else { src = A2 + (size_t)row * K2; kk = kg - K1; sc = s_scale[r]; }
                float4 x = *(const float4*)(src + kk);
                float4 y = *(const float4*)(src + kk + 4);
                vv[0] = x.x * sc; vv[1] = x.y * sc; vv[2] = x.z * sc; vv[3] = x.w * sc;
                vv[4] = y.x * sc; vv[5] = y.y * sc; vv[6] = y.z * sc; vv[7] = y.w * sc;
            } else {
#pragma unroll
                for (int j = 0; j < 8; j++) vv[j] = 0.f;
            }
            uint32_t hp[4], lp[4];
#pragma unroll
            for (int j = 0; j < 4; j++) {
                __nv_bfloat16 h0 = __float2bfloat16(vv[2 * j]);
                __nv_bfloat16 h1 = __float2bfloat16(vv[2 * j + 1]);
                __nv_bfloat162 hh = __halves2bfloat162(h0, h1);
                __nv_bfloat162 ll = __halves2bfloat162(
                    __float2bfloat16(vv[2 * j]     - __bfloat162float(h0)),
                    __float2bfloat16(vv[2 * j + 1] - __bfloat162float(h1)));
                hp[j] = *(uint32_t*)&hh;
                lp[j] = *(uint32_t*)&ll;
            }
            *(uint4*)&sAh[r * APAD + sub * 8] = make_uint4(hp[0], hp[1], hp[2], hp[3]);
            *(uint4*)&sAl[r * APAD + sub * 8] = make_uint4(lp[0], lp[1], lp[2], lp[3]);
        }
        // --- stage W (preconverted bf16, K-major [n][k])
#pragma unroll
        for (int half = 0; half < 2; half++) {
            int n = r0 + half * 64;
            size_t gi = (size_t)n * K + kg;
            *(uint4*)&sWh[n * APAD + sub * 8] = *(const uint4*)(Wh + gi);
            *(uint4*)&sWl[n * APAD + sub * 8] = *(const uint4*)(Wl + gi);
        }
        __syncthreads();

        // --- compute: 2 k-steps of 16
#pragma unroll
        for (int ks = 0; ks < 2; ks++) {
            int k0 = ks * 16;
            uint32_t a_off = ((lane & 15) * APAD + k0 + (lane >> 4) * 8) * 2;
            uint32_t ah[2][4], al[2][4];
#pragma unroll
            for (int mi = 0; mi < 2; mi++) {
                uint32_t ro = (wr * 32 + mi * 16) * APAD * 2;
                LDSM4(ah[mi], sAh_b + ro + a_off);
                LDSM4(al[mi], sAl_b + ro + a_off);
            }
#pragma unroll
            for (int bp = 0; bp < 4; bp++) {
                uint32_t no = (wc * 64 + bp * 16) * APAD * 2;
                uint32_t bh[4], bl[4];
                LDSM4(bh, sWh_b + no + a_off);
                LDSM4(bl, sWl_b + no + a_off);
#pragma unroll
                for (int mi = 0; mi < 2; mi++) {
                    MMA16816(acc[mi][2 * bp + 0], ah[mi], bh[0], bh[2]);
                    MMA16816(acc[mi][2 * bp + 0], ah[mi], bl[0], bl[2]);
                    MMA16816(acc[mi][2 * bp + 0], al[mi], bh[0], bh[2]);
                    MMA16816(acc[mi][2 * bp + 1], ah[mi], bh[1], bh[3]);
                    MMA16816(acc[mi][2 * bp + 1], ah[mi], bl[1], bl[3]);
                    MMA16816(acc[mi][2 * bp + 1], al[mi], bh[1], bh[3]);
                }
            }
        }
        __syncthreads();
    }

    // --- epilogue: bias + relu + fp32 stores (float2 per fragment half)
#pragma unroll
    for (int mi = 0; mi < 2; mi++) {
#pragma unroll
        for (int nj = 0; nj < 8; nj++) {
            int col = wc * 64 + nj * 8 + (lane & 3) * 2;
            float2 b = make_float2(0.f, 0.f);
            if (bias != nullptr) b = *(const float2*)(bias + col);
            int rowA = row0 + wr * 32 + mi * 16 + (lane >> 2);
            float* acc4 = acc[mi][nj];
            float2 o0, o1;
            o0.x = acc4[0] + b.x; o0.y = acc4[1] + b.y;
            o1.x = acc4[2] + b.x; o1.y = acc4[3] + b.y;
            if (do_relu) {
                o0.x = fmaxf(o0.x, 0.f); o0.y = fmaxf(o0.y, 0.f);
                o1.x = fmaxf(o1.x, 0.f); o1.y = fmaxf(o1.y, 0.f);
            }
            if (rowA < n_rows)
                *(float2*)(out + (size_t)rowA * out_stride + out_off + col) = o0;
            if (rowA + 8 < n_rows)
                *(float2*)(out + (size_t)(rowA + 8) * out_stride + out_off + col) = o1;
        }
    }
}

// ---------------------------------------------------------------------------
// edge1 + scatter2 fused: he1 = relu(P1[u]+Q1[v]+b1e) (registers only);
// msum2[v] += concat(hn1[u], he1)
__global__ void edge1_scatter2_kernel(const float* __restrict__ PQ1,
                                      const float* __restrict__ hn1,
                                      const float* __restrict__ b1e,
                                      const int* __restrict__ u,
                                      const int* __restrict__ v,
                                      float* __restrict__ msum2,
                                      int n_edges) {
    int e = (blockIdx.x * blockDim.x + threadIdx.x) >> 5;
    int lane = threadIdx.x & 31;
    if (e >= n_edges) return;
    int uu = u[e], vv = v[e];
    int j = lane * 4;
    float4 p = *(const float4*)(PQ1 + (size_t)uu * 256 + j);
    float4 q = *(const float4*)(PQ1 + (size_t)vv * 256 + 128 + j);
    float4 b = *(const float4*)(b1e + j);
    float4 h;
    h.x = fmaxf(p.x + q.x + b.x, 0.f);
    h.y = fmaxf(p.y + q.y + b.y, 0.f);
    h.z = fmaxf(p.z + q.z + b.z, 0.f);
    h.w = fmaxf(p.w + q.w + b.w, 0.f);
    float* d2 = msum2 + (size_t)vv * 256;
    red_add_v4(d2 + 128 + j, h);
    float4 hu = *(const float4*)(hn1 + (size_t)uu * 128 + j);
    red_add_v4(d2 + j, hu);
}

// ---------------------------------------------------------------------------
// edge2: he2 = relu(P2[u]+Q2[v]+b2e) -> out_he
__global__ void edge2_kernel(const float* __restrict__ PQ2,
                             const float* __restrict__ b2e,
                             const int* __restrict__ u,
                             const int* __restrict__ v,
                             float* __restrict__ out_he,
                             int n_edges) {
    int e = (blockIdx.x * blockDim.x + threadIdx.x) >> 5;
    int lane = threadIdx.x & 31;
    if (e >= n_edges) return;
    int uu = u[e], vv = v[e];
    int j = lane * 4;
    float4 p = *(const float4*)(PQ2 + (size_t)uu * 256 + j);
    float4 q = *(const float4*)(PQ2 + (size_t)vv * 256 + 128 + j);
    float4 b = *(const float4*)(b2e + j);
    float4 o;
    o.x = fmaxf(p.x + q.x + b.x, 0.f);
    o.y = fmaxf(p.y + q.y + b.y, 0.f);
    o.z = fmaxf(p.z + q.z + b.z, 0.f);
    o.w = fmaxf(p.w + q.w + b.w, 0.f);
    *(float4*)(out_he + (size_t)e * 128 + j) = o;
}

// ---------------------------------------------------------------------------
extern "C" void kernel_launch(void* const* d_in, const int* in_sizes, int n_in,
                              void* d_out, int out_size) {
    const float* nfeats = (const float*)d_in[0];
    const float* efeats = (const float*)d_in[1];
    const float* W1a_w  = (const float*)d_in[2];
    const float* W1a_b  = (const float*)d_in[3];
    const float* W1e_w  = (const float*)d_in[4];
    const float* W1e_b  = (const float*)d_in[5];
    const float* W2a_w  = (const float*)d_in[6];
    const float* W2a_b  = (const float*)d_in[7];
    const float* W2e_w  = (const float*)d_in[8];
    const float* W2e_b  = (const float*)d_in[9];
    const int*   u      = (const int*)d_in[10];
    const int*   v      = (const int*)d_in[11];
    float* out = (float*)d_out;

    float *msum1, *deg, *hn1, *PQ1, *msum2, *PQ2;
    __nv_bfloat16 *wth, *wtl;
    cudaGetSymbolAddress((void**)&msum1, g_msum1);
    cudaGetSymbolAddress((void**)&deg,   g_deg);
    cudaGetSymbolAddress((void**)&hn1,   g_hn1);
    cudaGetSymbolAddress((void**)&PQ1,   g_PQ1);
    cudaGetSymbolAddress((void**)&msum2, g_msum2);
    cudaGetSymbolAddress((void**)&PQ2,   g_PQ2);
    cudaGetSymbolAddress((void**)&wth,   g_wt_h);
    cudaGetSymbolAddress((void**)&wtl,   g_wt_l);

    const int N = N_NODES, E = N_EDGES;
    const int gx = (N + 127) / 128;           // 391 tiles
    const int edge_grid = (E * 32 + 255) / 256;

    // Weight blocks (element offsets = 128*K each):
    // W1a @0 (K=192), W1eP @24576, W1eQ @40960, W2a @57344 (K=384),
    // W2eP @106496, W2eQ @122880
    wconv_kernel<<<(128 * 192 + 255) / 256, 256>>>(W1a_w, 192, wth, wtl);
    wconv_kernel<<<(128 * 128 + 255) / 256, 256>>>(W1e_w, 128, wth + 24576, wtl + 24576);
    wconv_kernel<<<(128 * 128 + 255) / 256, 256>>>(W1e_w + 128 * 128, 128, wth + 40960, wtl + 40960);
    wconv_kernel<<<(128 * 384 + 255) / 256, 256>>>(W2a_w, 384, wth + 57344, wtl + 57344);
    wconv_kernel<<<(128 * 128 + 255) / 256, 256>>>(W2e_w, 128, wth + 106496, wtl + 106496);
    wconv_kernel<<<(128 * 128 + 255) / 256, 256>>>(W2e_w + 128 * 128, 128, wth + 122880, wtl + 122880);

    zero_kernel<<<2048, 256>>>((float4*)msum1, N * 128 / 4);
    zero_kernel<<<2048, 256>>>((float4*)msum2, N * 256 / 4);
    zero_kernel<<<64,   256>>>((float4*)deg,   N / 4);

    // Layer 1 aggregation
    scatter1_kernel<<<edge_grid, 256>>>(nfeats, efeats, u, v, msum1, deg, E);

    // hn1 = relu([nfeats | msum1/deg] @ W1a + b1a)
    gemm_mma_kernel<<<dim3(gx, 1), 256>>>(
        nfeats, 64, msum1, 128, deg, wth, wtl, 0, W1a_b, 1, hn1, 128, 0, N);
    // PQ1 = hn1 @ [W1e_top | W1e_bot]
    gemm_mma_kernel<<<dim3(gx, 2), 256>>>(
        hn1, 128, nullptr, 0, nullptr, wth + 24576, wtl + 24576, 128 * 128,
        nullptr, 0, PQ1, 256, 0, N);

    // he1 (registers) + layer-2 aggregation
    edge1_scatter2_kernel<<<edge_grid, 256>>>(PQ1, hn1, W1e_b, u, v, msum2, E);

    // hn2 = relu([hn1 | msum2/deg] @ W2a + b2a) -> d_out node block
    gemm_mma_kernel<<<dim3(gx, 1), 256>>>(
        hn1, 128, msum2, 256, deg, wth + 57344, wtl + 57344, 0, W2a_b, 1,
        out, 128, 0, N);
    // PQ2 = hn2 @ [W2e_top | W2e_bot]
    gemm_mma_kernel<<<dim3(gx, 2), 256>>>(
        out, 128, nullptr, 0, nullptr, wth + 106496, wtl + 106496, 128 * 128,
        nullptr, 0, PQ2, 256, 0, N);

    // he2 -> d_out edge block
    edge2_kernel<<<edge_grid, 256>>>(PQ2, W2e_b, u, v, out + (size_t)N * 128, E);
}